// round 15
// baseline (speedup 1.0000x reference)
#include <cuda_runtime.h>
#include <cuda_bf16.h>
#include <cstdint>

#define NB 32768
#define ND 512
#define NK 8192
#define CAP 64
#define MARGIN_S 4e-4f
#define NITEMS 2048          // 256 m-tiles x 8 n-chunks (1024 cols each)
#define FILTER_GRID 304

// ---------------- device scratch ----------------
__device__ float g_znorm[NB];
__device__ float g_wnorm[NK];
__device__ float g_partials[NB];
__device__ unsigned short g_zb[NB * ND];   // bf16 copies
__device__ unsigned short g_wb[NK * ND];
__device__ int g_cnt[NB];
__device__ int g_cand[NB * CAP];
__device__ unsigned g_rmax[NB];            // fkey-encoded running row max
__device__ int g_qhead;                    // work-queue head

// ---------------- helpers ----------------
__device__ __forceinline__ uint32_t smem_u32(const void* p) {
    uint32_t a;
    asm("{ .reg .u64 t; cvta.to.shared.u64 t, %1; cvt.u32.u64 %0, t; }" : "=r"(a) : "l"(p));
    return a;
}
__device__ __forceinline__ void cp16(uint32_t s, const void* g) {
    asm volatile("cp.async.cg.shared.global [%0], [%1], 16;" :: "r"(s), "l"(g));
}
__device__ __forceinline__ void cp_commit() { asm volatile("cp.async.commit_group;"); }
template <int N>
__device__ __forceinline__ void cp_wait() { asm volatile("cp.async.wait_group %0;" :: "n"(N)); }

__device__ __forceinline__ void ldmA(uint32_t* f, uint32_t addr) {
    asm volatile("ldmatrix.sync.aligned.m8n8.x4.shared.b16 {%0,%1,%2,%3}, [%4];"
                 : "=r"(f[0]), "=r"(f[1]), "=r"(f[2]), "=r"(f[3]) : "r"(addr));
}
__device__ __forceinline__ void ldmB(uint32_t* f, uint32_t addr) {
    asm volatile("ldmatrix.sync.aligned.m8n8.x2.shared.b16 {%0,%1}, [%2];"
                 : "=r"(f[0]), "=r"(f[1]) : "r"(addr));
}
__device__ __forceinline__ void mma16816(float* c, const uint32_t* a, const uint32_t* b) {
    asm volatile("mma.sync.aligned.m16n8k16.row.col.f32.bf16.bf16.f32 "
                 "{%0,%1,%2,%3}, {%4,%5,%6,%7}, {%8,%9}, {%0,%1,%2,%3};"
                 : "+f"(c[0]), "+f"(c[1]), "+f"(c[2]), "+f"(c[3])
                 : "r"(a[0]), "r"(a[1]), "r"(a[2]), "r"(a[3]), "r"(b[0]), "r"(b[1]));
}
__device__ __forceinline__ unsigned fkey(float x) {
    unsigned u = __float_as_uint(x);
    return (u & 0x80000000u) ? ~u : (u | 0x80000000u);
}
__device__ __forceinline__ float fdec(unsigned k) {
    return (k & 0x80000000u) ? __uint_as_float(k & 0x7fffffffu) : __uint_as_float(~k);
}

// ---------------- fp32 -> bf16 convert (z and W fused) ----------------
__global__ void conv_all(const float* __restrict__ z, const float* __restrict__ W,
                         unsigned short* __restrict__ zb, unsigned short* __restrict__ wb) {
    int i = blockIdx.x * blockDim.x + threadIdx.x;
    const int nz = NB * ND / 8;
    const int nw = NK * ND / 8;
    const float* src;
    unsigned short* dst;
    int j;
    if (i < nz) { src = z; dst = zb; j = i; }
    else if (i < nz + nw) { src = W; dst = wb; j = i - nz; }
    else return;
    const float4* s = reinterpret_cast<const float4*>(src) + j * 2;
    float4 a = __ldg(s), b = __ldg(s + 1);
    uint4 o;
    o.x = (uint32_t)__bfloat16_as_ushort(__float2bfloat16_rn(a.x)) |
          ((uint32_t)__bfloat16_as_ushort(__float2bfloat16_rn(a.y)) << 16);
    o.y = (uint32_t)__bfloat16_as_ushort(__float2bfloat16_rn(a.z)) |
          ((uint32_t)__bfloat16_as_ushort(__float2bfloat16_rn(a.w)) << 16);
    o.z = (uint32_t)__bfloat16_as_ushort(__float2bfloat16_rn(b.x)) |
          ((uint32_t)__bfloat16_as_ushort(__float2bfloat16_rn(b.y)) << 16);
    o.w = (uint32_t)__bfloat16_as_ushort(__float2bfloat16_rn(b.z)) |
          ((uint32_t)__bfloat16_as_ushort(__float2bfloat16_rn(b.w)) << 16);
    reinterpret_cast<uint4*>(dst)[j] = o;
}

// ---------------- row norms (exact, sequential), z+W fused, + resets ----------------
__global__ void norm_all(const float* __restrict__ z, const float* __restrict__ W) {
    int r = blockIdx.x * blockDim.x + threadIdx.x;
    const float* src;
    int row;
    if (r < NB) { src = z; row = r; }
    else if (r < NB + NK) { src = W; row = r - NB; }
    else return;
    const float4* p = reinterpret_cast<const float4*>(src + (size_t)row * ND);
    float acc = 0.f;
#pragma unroll 4
    for (int i = 0; i < ND / 4; i++) {
        float4 v = __ldg(p + i);
        acc = __fadd_rn(acc, __fmul_rn(v.x, v.x));
        acc = __fadd_rn(acc, __fmul_rn(v.y, v.y));
        acc = __fadd_rn(acc, __fmul_rn(v.z, v.z));
        acc = __fadd_rn(acc, __fmul_rn(v.w, v.w));
    }
    if (r < NB) {
        g_znorm[r] = acc;
        g_cnt[r] = 0;
        g_rmax[r] = 0u;
        if (r == 0) g_qhead = 0;
    } else {
        g_wnorm[row] = acc;
    }
}

// ---------------- HMMA filter: r11 body + prologue hoisted over epilogue ----------------
#define PITCH 80          // bytes per 32-col bf16 row (64B data + 16B pad)
#define TILE_BYTES (128 * PITCH)     // 10240
#define SMEM_DYN (6 * TILE_BYTES)    // 3 x (A + B) = 61440

__global__ __launch_bounds__(256, 2) void mma_filter() {
    extern __shared__ char dsm[];
    __shared__ int s_item;

    char* sA = dsm;                    // 3 x TILE_BYTES
    char* sB = dsm + 3 * TILE_BYTES;   // 3 x TILE_BYTES

    int tid = threadIdx.x, lid = tid & 31, wid = tid >> 5;
    int wm = wid >> 2, wn = wid & 3;     // warp grid 2 (m) x 4 (n)

    uint32_t aBase = smem_u32(sA);
    uint32_t bBase = smem_u32(sB);

    int r0 = tid >> 2, c0 = tid & 3;
    int r1 = (tid + 256) >> 2, c1 = (tid + 256) & 3;

    int lt = lid >> 3, l8 = lid & 7;
    int a_row_off = l8 + (lt & 1) * 8;
    int a_col_off = (lt >> 1) * 8;
    int b_row_off = l8;
    int b_col_off = (lt & 1) * 8;

    int g = lid >> 2, tc = (lid & 3) * 2;
    int lanebase = lid & ~3;

    for (;;) {
        if (tid == 0) s_item = atomicAdd(&g_qhead, 1);
        __syncthreads();
        int item = s_item;
        if (item >= NITEMS) break;
        int m0 = (item >> 3) * 128;
        int nt0 = (item & 7) * 8;         // 8 BN-tiles of 128 cols

        // prologue for nti = 0: k-blocks 0 and 1 into bufs 0 and 1
        {
            int nn = nt0 * 128;
#pragma unroll
            for (int p = 0; p < 2; p++) {
                int kk = p * 32;
                uint32_t aN = aBase + p * TILE_BYTES;
                uint32_t bN = bBase + p * TILE_BYTES;
                cp16(aN + r0 * PITCH + c0 * 16, g_zb + (size_t)(m0 + r0) * ND + kk + c0 * 8);
                cp16(aN + r1 * PITCH + c1 * 16, g_zb + (size_t)(m0 + r1) * ND + kk + c1 * 8);
                cp16(bN + r0 * PITCH + c0 * 16, g_wb + (size_t)(nn + r0) * ND + kk + c0 * 8);
                cp16(bN + r1 * PITCH + c1 * 16, g_wb + (size_t)(nn + r1) * ND + kk + c1 * 8);
                cp_commit();
            }
        }

        for (int nti = 0; nti < 8; nti++) {
            int n0 = (nt0 + nti) * 128;
            float acc[4][4][4];
#pragma unroll
            for (int mt = 0; mt < 4; mt++)
#pragma unroll
                for (int nt = 0; nt < 4; nt++)
#pragma unroll
                    for (int q = 0; q < 4; q++) acc[mt][nt][q] = 0.f;

            for (int kb = 0; kb < 16; kb++) {
                if (kb < 15) cp_wait<1>(); else cp_wait<0>();
                __syncthreads();    // kb data visible; step kb-1 readers all done

                int cb3 = kb % 3;
                uint32_t aCur = aBase + cb3 * TILE_BYTES;
                uint32_t bCur = bBase + cb3 * TILE_BYTES;

                // ---- ks = 0 ----
                {
                    uint32_t af[4][4], bf[4][2];
#pragma unroll
                    for (int mt = 0; mt < 4; mt++) {
                        int row = wm * 64 + mt * 16 + a_row_off;
                        ldmA(af[mt], aCur + row * PITCH + a_col_off * 2);
                    }
#pragma unroll
                    for (int nt = 0; nt < 4; nt++) {
                        int row = wn * 32 + nt * 8 + b_row_off;
                        ldmB(bf[nt], bCur + row * PITCH + b_col_off * 2);
                    }
#pragma unroll
                    for (int mt = 0; mt < 4; mt++)
#pragma unroll
                        for (int nt = 0; nt < 4; nt++)
                            mma16816(acc[mt][nt], af[mt], bf[nt]);
                }

                // cp.async for kb+2 issued INSIDE the tensor phase
                if (kb + 2 < 16) {
                    int kk = (kb + 2) * 32;
                    int bi3 = (kb + 2) % 3;
                    uint32_t aN = aBase + bi3 * TILE_BYTES;
                    uint32_t bN = bBase + bi3 * TILE_BYTES;
                    cp16(aN + r0 * PITCH + c0 * 16, g_zb + (size_t)(m0 + r0) * ND + kk + c0 * 8);
                    cp16(aN + r1 * PITCH + c1 * 16, g_zb + (size_t)(m0 + r1) * ND + kk + c1 * 8);
                    cp16(bN + r0 * PITCH + c0 * 16, g_wb + (size_t)(n0 + r0) * ND + kk + c0 * 8);
                    cp16(bN + r1 * PITCH + c1 * 16, g_wb + (size_t)(n0 + r1) * ND + kk + c1 * 8);
                    cp_commit();
                }

                // ---- ks = 1 ----
                {
                    uint32_t af[4][4], bf[4][2];
#pragma unroll
                    for (int mt = 0; mt < 4; mt++) {
                        int row = wm * 64 + mt * 16 + a_row_off;
                        ldmA(af[mt], aCur + row * PITCH + (16 + a_col_off) * 2);
                    }
#pragma unroll
                    for (int nt = 0; nt < 4; nt++) {
                        int row = wn * 32 + nt * 8 + b_row_off;
                        ldmB(bf[nt], bCur + row * PITCH + (16 + b_col_off) * 2);
                    }
#pragma unroll
                    for (int mt = 0; mt < 4; mt++)
#pragma unroll
                        for (int nt = 0; nt < 4; nt++)
                            mma16816(acc[mt][nt], af[mt], bf[nt]);
                }
            }
            __syncthreads();   // all reads of bufs done (kb15 used buf0, kb13 buf1)

            // HOISTED prologue for nti+1: overlaps the epilogue's ATOMG latency.
            // Safe: bufs 0/1's last readers (kb15 / kb13) are past the barrier.
            if (nti < 7) {
                int nn = (nt0 + nti + 1) * 128;
#pragma unroll
                for (int p = 0; p < 2; p++) {
                    int kk = p * 32;
                    uint32_t aN = aBase + p * TILE_BYTES;
                    uint32_t bN = bBase + p * TILE_BYTES;
                    cp16(aN + r0 * PITCH + c0 * 16, g_zb + (size_t)(m0 + r0) * ND + kk + c0 * 8);
                    cp16(aN + r1 * PITCH + c1 * 16, g_zb + (size_t)(m0 + r1) * ND + kk + c1 * 8);
                    cp16(bN + r0 * PITCH + c0 * 16, g_wb + (size_t)(nn + r0) * ND + kk + c0 * 8);
                    cp16(bN + r1 * PITCH + c1 * 16, g_wb + (size_t)(nn + r1) * ND + kk + c1 * 8);
                    cp_commit();
                }
            }

            // epilogue: 4-lane shuffle max -> one global atomicMax per row
#pragma unroll
            for (int mt = 0; mt < 4; mt++) {
#pragma unroll
                for (int h = 0; h < 2; h++) {
                    float v8[8];
                    float m8 = -1e30f;
#pragma unroll
                    for (int nt = 0; nt < 4; nt++)
#pragma unroll
                        for (int cc = 0; cc < 2; cc++) {
                            float v = acc[mt][nt][h * 2 + cc];
                            v8[nt * 2 + cc] = v;
                            m8 = fmaxf(m8, v);
                        }
                    m8 = fmaxf(m8, __shfl_xor_sync(0xffffffffu, m8, 1));
                    m8 = fmaxf(m8, __shfl_xor_sync(0xffffffffu, m8, 2));
                    int grow = m0 + wm * 64 + mt * 16 + h * 8 + g;
                    unsigned old = 0u;
                    if ((lid & 3) == 0) old = atomicMax(&g_rmax[grow], fkey(m8));
                    float cur = fmaxf(m8, fdec(old));   // fdec(0)=NaN -> picks m8
                    float th = __shfl_sync(0xffffffffu, cur, lanebase) - MARGIN_S;
#pragma unroll
                    for (int nt = 0; nt < 4; nt++)
#pragma unroll
                        for (int cc = 0; cc < 2; cc++) {
                            if (v8[nt * 2 + cc] >= th) {
                                int slot = atomicAdd(&g_cnt[grow], 1);
                                if (slot < CAP)
                                    g_cand[grow * CAP + slot] = n0 + wn * 32 + nt * 8 + tc + cc;
                            }
                        }
                }
            }
        }
    }
}

// ---------------- fused exact rescoring + gather + partials ----------------
__global__ __launch_bounds__(256) void exact_gather(const float* __restrict__ z,
                                                    const float* __restrict__ W,
                                                    float* __restrict__ out, int out_size) {
    __shared__ float zs[8][ND];
    int wrp = threadIdx.x >> 5, lid = threadIdx.x & 31;
    int row = blockIdx.x * 8 + wrp;
    if (row >= NB) return;

    float4* zd = reinterpret_cast<float4*>(zs[wrp]);
    const float4* zsrc = reinterpret_cast<const float4*>(z + (size_t)row * ND);
#pragma unroll
    for (int i = 0; i < ND / 4 / 32; i++) zd[lid + i * 32] = __ldg(zsrc + lid + i * 32);
    __syncwarp();

    int cnt = g_cnt[row];
    float zn = g_znorm[row];
    float best = __int_as_float(0x7f800000);
    int bi = 0x7fffffff;

    if (cnt <= CAP) {
        for (int s = lid; s < cnt; s += 32) {
            int k = g_cand[row * CAP + s];
            const float4* wr = reinterpret_cast<const float4*>(W + (size_t)k * ND);
            float acc = 0.f;
#pragma unroll 4
            for (int d = 0; d < ND / 4; d++) {
                float4 wv = __ldg(wr + d);
                float4 zv = zd[d];
                acc = __fmaf_rn(zv.x, wv.x, acc);
                acc = __fmaf_rn(zv.y, wv.y, acc);
                acc = __fmaf_rn(zv.z, wv.z, acc);
                acc = __fmaf_rn(zv.w, wv.w, acc);
            }
            float d2 = __fsub_rn(__fadd_rn(zn, g_wnorm[k]), __fmul_rn(2.0f, acc));
            if (d2 < best || (d2 == best && k < bi)) { best = d2; bi = k; }
        }
    } else {
        for (int k = lid; k < NK; k += 32) {
            const float4* wr = reinterpret_cast<const float4*>(W + (size_t)k * ND);
            float acc = 0.f;
#pragma unroll 4
            for (int d = 0; d < ND / 4; d++) {
                float4 wv = __ldg(wr + d);
                float4 zv = zd[d];
                acc = __fmaf_rn(zv.x, wv.x, acc);
                acc = __fmaf_rn(zv.y, wv.y, acc);
                acc = __fmaf_rn(zv.z, wv.z, acc);
                acc = __fmaf_rn(zv.w, wv.w, acc);
            }
            float d2 = __fsub_rn(__fadd_rn(zn, g_wnorm[k]), __fmul_rn(2.0f, acc));
            if (d2 < best || (d2 == best && k < bi)) { best = d2; bi = k; }
        }
    }
#pragma unroll
    for (int off = 16; off > 0; off >>= 1) {
        float ov = __shfl_down_sync(0xffffffffu, best, off);
        int oi = __shfl_down_sync(0xffffffffu, bi, off);
        if (ov < best || (ov == best && oi < bi)) { best = ov; bi = oi; }
    }
    bi = __shfl_sync(0xffffffffu, bi, 0);

    // gather + straight-through rounding + loss partial (z from smem)
    const float4* wr = reinterpret_cast<const float4*>(W + (size_t)bi * ND);
    float4* od = reinterpret_cast<float4*>(out + (size_t)row * ND);
    float s = 0.f;
#pragma unroll
    for (int i = 0; i < ND / 4 / 32; i++) {
        int j = lid + i * 32;
        float4 wv = __ldg(wr + j);
        float4 zv = zd[j];
        float dx = __fsub_rn(wv.x, zv.x);
        float dy = __fsub_rn(wv.y, zv.y);
        float dz = __fsub_rn(wv.z, zv.z);
        float dw = __fsub_rn(wv.w, zv.w);
        float4 o;
        o.x = __fadd_rn(zv.x, dx);
        o.y = __fadd_rn(zv.y, dy);
        o.z = __fadd_rn(zv.z, dz);
        o.w = __fadd_rn(zv.w, dw);
        od[j] = o;
        s = __fmaf_rn(dx, dx, s);
        s = __fmaf_rn(dy, dy, s);
        s = __fmaf_rn(dz, dz, s);
        s = __fmaf_rn(dw, dw, s);
    }
#pragma unroll
    for (int off = 16; off > 0; off >>= 1)
        s += __shfl_down_sync(0xffffffffu, s, off);
    if (lid == 0) {
        g_partials[row] = s;
        size_t off = (size_t)NB * ND + row;
        if (off < (size_t)out_size) out[off] = (float)bi;
    }
}

// ---------------- final loss reduce (1024 threads, vectorized) ----------------
__global__ void loss_reduce(float* __restrict__ out, int out_size) {
    __shared__ float sm[1024];
    int t = threadIdx.x;
    const float4* p = reinterpret_cast<const float4*>(g_partials);
    float s = 0.f;
#pragma unroll
    for (int i = 0; i < NB / 4 / 1024; i++) {
        float4 v = p[t + i * 1024];
        s += v.x + v.y + v.z + v.w;
    }
    sm[t] = s;
    __syncthreads();
    for (int o = 512; o > 0; o >>= 1) {
        if (t < o) sm[t] += sm[t + o];
        __syncthreads();
    }
    if (t == 0) {
        size_t off = (size_t)NB * ND + NB;
        if (off < (size_t)out_size)
            out[off] = 1.25f * (sm[0] / (float)((size_t)NB * ND));
    }
}

// ---------------- launch ----------------
extern "C" void kernel_launch(void* const* d_in, const int* in_sizes, int n_in,
                              void* d_out, int out_size) {
    const float* z = (const float*)d_in[0];
    const float* W = (const float*)d_in[1];
    float* out = (float*)d_out;

    static int smem_set = 0;
    if (!smem_set) {
        cudaFuncSetAttribute(mma_filter, cudaFuncAttributeMaxDynamicSharedMemorySize, SMEM_DYN);
        smem_set = 1;
    }

    unsigned short* zb_ptr = nullptr;
    unsigned short* wb_ptr = nullptr;
    cudaGetSymbolAddress((void**)&zb_ptr, g_zb);
    cudaGetSymbolAddress((void**)&wb_ptr, g_wb);

    conv_all<<<((NB + NK) * (ND / 8) + 255) / 256, 256>>>(z, W, zb_ptr, wb_ptr);
    norm_all<<<(NB + NK) / 128, 128>>>(z, W);
    mma_filter<<<FILTER_GRID, 256, SMEM_DYN>>>();
    exact_gather<<<NB / 8, 256>>>(z, W, out, out_size);
    loss_reduce<<<1, 1024>>>(out, out_size);
}

// round 16
// speedup vs baseline: 1.0395x; 1.0395x over previous
#include <cuda_runtime.h>
#include <cuda_bf16.h>
#include <cstdint>

#define NB 32768
#define ND 512
#define NK 8192
#define CAP 192
#define MARGIN_S 4e-4f
#define NITEMS 2048          // 256 m-tiles x 8 n-chunks (1024 cols each)
#define FILTER_GRID 304

// ---------------- device scratch ----------------
__device__ float g_znorm[NB];
__device__ float g_wnorm[NK];
__device__ float g_partials[NB];
__device__ unsigned short g_zb[NB * ND];   // bf16 copies
__device__ unsigned short g_wb[NK * ND];
__device__ int g_cnt[NB];
__device__ int g_cand[NB * CAP];
__device__ unsigned g_rmax[NB];            // fkey-encoded running row max
__device__ int g_qhead;                    // work-queue head

// ---------------- helpers ----------------
__device__ __forceinline__ uint32_t smem_u32(const void* p) {
    uint32_t a;
    asm("{ .reg .u64 t; cvta.to.shared.u64 t, %1; cvt.u32.u64 %0, t; }" : "=r"(a) : "l"(p));
    return a;
}
__device__ __forceinline__ void cp16(uint32_t s, const void* g) {
    asm volatile("cp.async.cg.shared.global [%0], [%1], 16;" :: "r"(s), "l"(g));
}
__device__ __forceinline__ void cp_commit() { asm volatile("cp.async.commit_group;"); }
template <int N>
__device__ __forceinline__ void cp_wait() { asm volatile("cp.async.wait_group %0;" :: "n"(N)); }

__device__ __forceinline__ void ldmA(uint32_t* f, uint32_t addr) {
    asm volatile("ldmatrix.sync.aligned.m8n8.x4.shared.b16 {%0,%1,%2,%3}, [%4];"
                 : "=r"(f[0]), "=r"(f[1]), "=r"(f[2]), "=r"(f[3]) : "r"(addr));
}
__device__ __forceinline__ void ldmB(uint32_t* f, uint32_t addr) {
    asm volatile("ldmatrix.sync.aligned.m8n8.x2.shared.b16 {%0,%1}, [%2];"
                 : "=r"(f[0]), "=r"(f[1]) : "r"(addr));
}
__device__ __forceinline__ void mma16816(float* c, const uint32_t* a, const uint32_t* b) {
    asm volatile("mma.sync.aligned.m16n8k16.row.col.f32.bf16.bf16.f32 "
                 "{%0,%1,%2,%3}, {%4,%5,%6,%7}, {%8,%9}, {%0,%1,%2,%3};"
                 : "+f"(c[0]), "+f"(c[1]), "+f"(c[2]), "+f"(c[3])
                 : "r"(a[0]), "r"(a[1]), "r"(a[2]), "r"(a[3]), "r"(b[0]), "r"(b[1]));
}
__device__ __forceinline__ unsigned fkey(float x) {
    unsigned u = __float_as_uint(x);
    return (u & 0x80000000u) ? ~u : (u | 0x80000000u);
}
__device__ __forceinline__ float fdec(unsigned k) {
    return (k & 0x80000000u) ? __uint_as_float(k & 0x7fffffffu) : __uint_as_float(~k);
}

// ---------------- fp32 -> bf16 convert (z and W fused) ----------------
__global__ void conv_all(const float* __restrict__ z, const float* __restrict__ W,
                         unsigned short* __restrict__ zb, unsigned short* __restrict__ wb) {
    int i = blockIdx.x * blockDim.x + threadIdx.x;
    const int nz = NB * ND / 8;
    const int nw = NK * ND / 8;
    const float* src;
    unsigned short* dst;
    int j;
    if (i < nz) { src = z; dst = zb; j = i; }
    else if (i < nz + nw) { src = W; dst = wb; j = i - nz; }
    else return;
    const float4* s = reinterpret_cast<const float4*>(src) + j * 2;
    float4 a = __ldg(s), b = __ldg(s + 1);
    uint4 o;
    o.x = (uint32_t)__bfloat16_as_ushort(__float2bfloat16_rn(a.x)) |
          ((uint32_t)__bfloat16_as_ushort(__float2bfloat16_rn(a.y)) << 16);
    o.y = (uint32_t)__bfloat16_as_ushort(__float2bfloat16_rn(a.z)) |
          ((uint32_t)__bfloat16_as_ushort(__float2bfloat16_rn(a.w)) << 16);
    o.z = (uint32_t)__bfloat16_as_ushort(__float2bfloat16_rn(b.x)) |
          ((uint32_t)__bfloat16_as_ushort(__float2bfloat16_rn(b.y)) << 16);
    o.w = (uint32_t)__bfloat16_as_ushort(__float2bfloat16_rn(b.z)) |
          ((uint32_t)__bfloat16_as_ushort(__float2bfloat16_rn(b.w)) << 16);
    reinterpret_cast<uint4*>(dst)[j] = o;
}

// ---------------- row norms (exact, sequential), z+W fused, + resets ----------------
__global__ void norm_all(const float* __restrict__ z, const float* __restrict__ W) {
    int r = blockIdx.x * blockDim.x + threadIdx.x;
    const float* src;
    int row;
    if (r < NB) { src = z; row = r; }
    else if (r < NB + NK) { src = W; row = r - NB; }
    else return;
    const float4* p = reinterpret_cast<const float4*>(src + (size_t)row * ND);
    float acc = 0.f;
#pragma unroll 4
    for (int i = 0; i < ND / 4; i++) {
        float4 v = __ldg(p + i);
        acc = __fadd_rn(acc, __fmul_rn(v.x, v.x));
        acc = __fadd_rn(acc, __fmul_rn(v.y, v.y));
        acc = __fadd_rn(acc, __fmul_rn(v.z, v.z));
        acc = __fadd_rn(acc, __fmul_rn(v.w, v.w));
    }
    if (r < NB) {
        g_znorm[r] = acc;
        g_cnt[r] = 0;
        g_rmax[r] = 0u;
        if (r == 0) g_qhead = 0;
    } else {
        g_wnorm[row] = acc;
    }
}

// ---------------- HMMA filter: r11 body verbatim ----------------
#define PITCH 80          // bytes per 32-col bf16 row (64B data + 16B pad)
#define TILE_BYTES (128 * PITCH)     // 10240
#define SMEM_DYN (6 * TILE_BYTES)    // 3 x (A + B) = 61440

__global__ __launch_bounds__(256, 2) void mma_filter() {
    extern __shared__ char dsm[];
    __shared__ int s_item;

    char* sA = dsm;                    // 3 x TILE_BYTES
    char* sB = dsm + 3 * TILE_BYTES;   // 3 x TILE_BYTES

    int tid = threadIdx.x, lid = tid & 31, wid = tid >> 5;
    int wm = wid >> 2, wn = wid & 3;     // warp grid 2 (m) x 4 (n)

    uint32_t aBase = smem_u32(sA);
    uint32_t bBase = smem_u32(sB);

    int r0 = tid >> 2, c0 = tid & 3;
    int r1 = (tid + 256) >> 2, c1 = (tid + 256) & 3;

    int lt = lid >> 3, l8 = lid & 7;
    int a_row_off = l8 + (lt & 1) * 8;
    int a_col_off = (lt >> 1) * 8;
    int b_row_off = l8;
    int b_col_off = (lt & 1) * 8;

    int g = lid >> 2, tc = (lid & 3) * 2;
    int lanebase = lid & ~3;

    for (;;) {
        if (tid == 0) s_item = atomicAdd(&g_qhead, 1);
        __syncthreads();
        int item = s_item;
        if (item >= NITEMS) break;
        int m0 = (item >> 3) * 128;
        int nt0 = (item & 7) * 8;         // 8 BN-tiles of 128 cols

        for (int nti = 0; nti < 8; nti++) {
            int n0 = (nt0 + nti) * 128;
            float acc[4][4][4];
#pragma unroll
            for (int mt = 0; mt < 4; mt++)
#pragma unroll
                for (int nt = 0; nt < 4; nt++)
#pragma unroll
                    for (int q = 0; q < 4; q++) acc[mt][nt][q] = 0.f;

            // prologue: k-blocks 0 and 1 into bufs 0 and 1
#pragma unroll
            for (int p = 0; p < 2; p++) {
                int kk = p * 32;
                uint32_t aN = aBase + p * TILE_BYTES;
                uint32_t bN = bBase + p * TILE_BYTES;
                cp16(aN + r0 * PITCH + c0 * 16, g_zb + (size_t)(m0 + r0) * ND + kk + c0 * 8);
                cp16(aN + r1 * PITCH + c1 * 16, g_zb + (size_t)(m0 + r1) * ND + kk + c1 * 8);
                cp16(bN + r0 * PITCH + c0 * 16, g_wb + (size_t)(n0 + r0) * ND + kk + c0 * 8);
                cp16(bN + r1 * PITCH + c1 * 16, g_wb + (size_t)(n0 + r1) * ND + kk + c1 * 8);
                cp_commit();
            }

            for (int kb = 0; kb < 16; kb++) {
                if (kb < 15) cp_wait<1>(); else cp_wait<0>();
                __syncthreads();    // kb data visible; step kb-1 readers all done

                int cb3 = kb % 3;
                uint32_t aCur = aBase + cb3 * TILE_BYTES;
                uint32_t bCur = bBase + cb3 * TILE_BYTES;

                // ---- ks = 0 ----
                {
                    uint32_t af[4][4], bf[4][2];
#pragma unroll
                    for (int mt = 0; mt < 4; mt++) {
                        int row = wm * 64 + mt * 16 + a_row_off;
                        ldmA(af[mt], aCur + row * PITCH + a_col_off * 2);
                    }
#pragma unroll
                    for (int nt = 0; nt < 4; nt++) {
                        int row = wn * 32 + nt * 8 + b_row_off;
                        ldmB(bf[nt], bCur + row * PITCH + b_col_off * 2);
                    }
#pragma unroll
                    for (int mt = 0; mt < 4; mt++)
#pragma unroll
                        for (int nt = 0; nt < 4; nt++)
                            mma16816(acc[mt][nt], af[mt], bf[nt]);
                }

                // cp.async for kb+2 issued INSIDE the tensor phase
                if (kb + 2 < 16) {
                    int kk = (kb + 2) * 32;
                    int bi3 = (kb + 2) % 3;
                    uint32_t aN = aBase + bi3 * TILE_BYTES;
                    uint32_t bN = bBase + bi3 * TILE_BYTES;
                    cp16(aN + r0 * PITCH + c0 * 16, g_zb + (size_t)(m0 + r0) * ND + kk + c0 * 8);
                    cp16(aN + r1 * PITCH + c1 * 16, g_zb + (size_t)(m0 + r1) * ND + kk + c1 * 8);
                    cp16(bN + r0 * PITCH + c0 * 16, g_wb + (size_t)(n0 + r0) * ND + kk + c0 * 8);
                    cp16(bN + r1 * PITCH + c1 * 16, g_wb + (size_t)(n0 + r1) * ND + kk + c1 * 8);
                    cp_commit();
                }

                // ---- ks = 1 ----
                {
                    uint32_t af[4][4], bf[4][2];
#pragma unroll
                    for (int mt = 0; mt < 4; mt++) {
                        int row = wm * 64 + mt * 16 + a_row_off;
                        ldmA(af[mt], aCur + row * PITCH + (16 + a_col_off) * 2);
                    }
#pragma unroll
                    for (int nt = 0; nt < 4; nt++) {
                        int row = wn * 32 + nt * 8 + b_row_off;
                        ldmB(bf[nt], bCur + row * PITCH + (16 + b_col_off) * 2);
                    }
#pragma unroll
                    for (int mt = 0; mt < 4; mt++)
#pragma unroll
                        for (int nt = 0; nt < 4; nt++)
                            mma16816(acc[mt][nt], af[mt], bf[nt]);
                }
            }
            __syncthreads();   // readers done before next ntile/item reuses bufs

            // epilogue: 4-lane shuffle max -> one global atomicMax per row
#pragma unroll
            for (int mt = 0; mt < 4; mt++) {
#pragma unroll
                for (int h = 0; h < 2; h++) {
                    float v8[8];
                    float m8 = -1e30f;
#pragma unroll
                    for (int nt = 0; nt < 4; nt++)
#pragma unroll
                        for (int cc = 0; cc < 2; cc++) {
                            float v = acc[mt][nt][h * 2 + cc];
                            v8[nt * 2 + cc] = v;
                            m8 = fmaxf(m8, v);
                        }
                    m8 = fmaxf(m8, __shfl_xor_sync(0xffffffffu, m8, 1));
                    m8 = fmaxf(m8, __shfl_xor_sync(0xffffffffu, m8, 2));
                    int grow = m0 + wm * 64 + mt * 16 + h * 8 + g;
                    unsigned old = 0u;
                    if ((lid & 3) == 0) old = atomicMax(&g_rmax[grow], fkey(m8));
                    float cur = fmaxf(m8, fdec(old));   // fdec(0)=NaN -> picks m8
                    float th = __shfl_sync(0xffffffffu, cur, lanebase) - MARGIN_S;
#pragma unroll
                    for (int nt = 0; nt < 4; nt++)
#pragma unroll
                        for (int cc = 0; cc < 2; cc++) {
                            if (v8[nt * 2 + cc] >= th) {
                                int slot = atomicAdd(&g_cnt[grow], 1);
                                if (slot < CAP)
                                    g_cand[grow * CAP + slot] = n0 + wn * 32 + nt * 8 + tc + cc;
                            }
                        }
                }
            }
        }
    }
}

// ---------------- fused exact rescoring + gather + partials ----------------
// CAP=192: fallback full-scan becomes practically unreachable, killing the
// 270us single-warp straggler identified in r15's profile.
__global__ __launch_bounds__(256) void exact_gather(const float* __restrict__ z,
                                                    const float* __restrict__ W,
                                                    float* __restrict__ out, int out_size) {
    __shared__ float zs[8][ND];
    int wrp = threadIdx.x >> 5, lid = threadIdx.x & 31;
    int row = blockIdx.x * 8 + wrp;
    if (row >= NB) return;

    float4* zd = reinterpret_cast<float4*>(zs[wrp]);
    const float4* zsrc = reinterpret_cast<const float4*>(z + (size_t)row * ND);
#pragma unroll
    for (int i = 0; i < ND / 4 / 32; i++) zd[lid + i * 32] = __ldg(zsrc + lid + i * 32);
    __syncwarp();

    int cnt = g_cnt[row];
    float zn = g_znorm[row];
    float best = __int_as_float(0x7f800000);
    int bi = 0x7fffffff;

    if (cnt <= CAP) {
        for (int s = lid; s < cnt; s += 32) {
            int k = g_cand[row * CAP + s];
            const float4* wr = reinterpret_cast<const float4*>(W + (size_t)k * ND);
            float acc = 0.f;
#pragma unroll 4
            for (int d = 0; d < ND / 4; d++) {
                float4 wv = __ldg(wr + d);
                float4 zv = zd[d];
                acc = __fmaf_rn(zv.x, wv.x, acc);
                acc = __fmaf_rn(zv.y, wv.y, acc);
                acc = __fmaf_rn(zv.z, wv.z, acc);
                acc = __fmaf_rn(zv.w, wv.w, acc);
            }
            float d2 = __fsub_rn(__fadd_rn(zn, g_wnorm[k]), __fmul_rn(2.0f, acc));
            if (d2 < best || (d2 == best && k < bi)) { best = d2; bi = k; }
        }
    } else {
        for (int k = lid; k < NK; k += 32) {
            const float4* wr = reinterpret_cast<const float4*>(W + (size_t)k * ND);
            float acc = 0.f;
#pragma unroll 4
            for (int d = 0; d < ND / 4; d++) {
                float4 wv = __ldg(wr + d);
                float4 zv = zd[d];
                acc = __fmaf_rn(zv.x, wv.x, acc);
                acc = __fmaf_rn(zv.y, wv.y, acc);
                acc = __fmaf_rn(zv.z, wv.z, acc);
                acc = __fmaf_rn(zv.w, wv.w, acc);
            }
            float d2 = __fsub_rn(__fadd_rn(zn, g_wnorm[k]), __fmul_rn(2.0f, acc));
            if (d2 < best || (d2 == best && k < bi)) { best = d2; bi = k; }
        }
    }
#pragma unroll
    for (int off = 16; off > 0; off >>= 1) {
        float ov = __shfl_down_sync(0xffffffffu, best, off);
        int oi = __shfl_down_sync(0xffffffffu, bi, off);
        if (ov < best || (ov == best && oi < bi)) { best = ov; bi = oi; }
    }
    bi = __shfl_sync(0xffffffffu, bi, 0);

    // gather + straight-through rounding + loss partial (z from smem)
    const float4* wr = reinterpret_cast<const float4*>(W + (size_t)bi * ND);
    float4* od = reinterpret_cast<float4*>(out + (size_t)row * ND);
    float s = 0.f;
#pragma unroll
    for (int i = 0; i < ND / 4 / 32; i++) {
        int j = lid + i * 32;
        float4 wv = __ldg(wr + j);
        float4 zv = zd[j];
        float dx = __fsub_rn(wv.x, zv.x);
        float dy = __fsub_rn(wv.y, zv.y);
        float dz = __fsub_rn(wv.z, zv.z);
        float dw = __fsub_rn(wv.w, zv.w);
        float4 o;
        o.x = __fadd_rn(zv.x, dx);
        o.y = __fadd_rn(zv.y, dy);
        o.z = __fadd_rn(zv.z, dz);
        o.w = __fadd_rn(zv.w, dw);
        od[j] = o;
        s = __fmaf_rn(dx, dx, s);
        s = __fmaf_rn(dy, dy, s);
        s = __fmaf_rn(dz, dz, s);
        s = __fmaf_rn(dw, dw, s);
    }
#pragma unroll
    for (int off = 16; off > 0; off >>= 1)
        s += __shfl_down_sync(0xffffffffu, s, off);
    if (lid == 0) {
        g_partials[row] = s;
        size_t off = (size_t)NB * ND + row;
        if (off < (size_t)out_size) out[off] = (float)bi;
    }
}

// ---------------- final loss reduce (1024 threads, vectorized) ----------------
__global__ void loss_reduce(float* __restrict__ out, int out_size) {
    __shared__ float sm[1024];
    int t = threadIdx.x;
    const float4* p = reinterpret_cast<const float4*>(g_partials);
    float s = 0.f;
#pragma unroll
    for (int i = 0; i < NB / 4 / 1024; i++) {
        float4 v = p[t + i * 1024];
        s += v.x + v.y + v.z + v.w;
    }
    sm[t] = s;
    __syncthreads();
    for (int o = 512; o > 0; o >>= 1) {
        if (t < o) sm[t] += sm[t + o];
        __syncthreads();
    }
    if (t == 0) {
        size_t off = (size_t)NB * ND + NB;
        if (off < (size_t)out_size)
            out[off] = 1.25f * (sm[0] / (float)((size_t)NB * ND));
    }
}

// ---------------- launch ----------------
// exact_gather is the 4th launch (ncu capture slot) to verify the CAP fix.
extern "C" void kernel_launch(void* const* d_in, const int* in_sizes, int n_in,
                              void* d_out, int out_size) {
    const float* z = (const float*)d_in[0];
    const float* W = (const float*)d_in[1];
    float* out = (float*)d_out;

    static int smem_set = 0;
    if (!smem_set) {
        cudaFuncSetAttribute(mma_filter, cudaFuncAttributeMaxDynamicSharedMemorySize, SMEM_DYN);
        smem_set = 1;
    }

    unsigned short* zb_ptr = nullptr;
    unsigned short* wb_ptr = nullptr;
    cudaGetSymbolAddress((void**)&zb_ptr, g_zb);
    cudaGetSymbolAddress((void**)&wb_ptr, g_wb);

    conv_all<<<((NB + NK) * (ND / 8) + 255) / 256, 256>>>(z, W, zb_ptr, wb_ptr);
    norm_all<<<(NB + NK) / 128, 128>>>(z, W);
    mma_filter<<<FILTER_GRID, 256, SMEM_DYN>>>();
    exact_gather<<<NB / 8, 256>>>(z, W, out, out_size);
    loss_reduce<<<1, 1024>>>(out, out_size);
}

// round 17
// speedup vs baseline: 1.1475x; 1.1039x over previous
#include <cuda_runtime.h>
#include <cuda_bf16.h>
#include <cstdint>

#define NB 32768
#define ND 512
#define NK 8192
#define CAP 192
#define MARGIN_S 4e-4f
#define NITEMS 2048          // 256 m-tiles x 8 n-chunks (1024 cols each)
#define FILTER_GRID 304

// ---------------- device scratch ----------------
__device__ float g_znorm[NB];
__device__ float g_wnorm[NK];
__device__ float g_partials[NB];
__device__ unsigned short g_zb[NB * ND];   // bf16 copies
__device__ unsigned short g_wb[NK * ND];
__device__ int g_cnt[NB];
__device__ int g_cand[NB * CAP];
__device__ float g_cscore[NB * CAP];       // bf16-filter score of each candidate
__device__ unsigned g_rmax[NB];            // fkey-encoded running row max
__device__ int g_qhead;                    // work-queue head

// ---------------- helpers ----------------
__device__ __forceinline__ uint32_t smem_u32(const void* p) {
    uint32_t a;
    asm("{ .reg .u64 t; cvta.to.shared.u64 t, %1; cvt.u32.u64 %0, t; }" : "=r"(a) : "l"(p));
    return a;
}
__device__ __forceinline__ void cp16(uint32_t s, const void* g) {
    asm volatile("cp.async.cg.shared.global [%0], [%1], 16;" :: "r"(s), "l"(g));
}
__device__ __forceinline__ void cp_commit() { asm volatile("cp.async.commit_group;"); }
template <int N>
__device__ __forceinline__ void cp_wait() { asm volatile("cp.async.wait_group %0;" :: "n"(N)); }

__device__ __forceinline__ void ldmA(uint32_t* f, uint32_t addr) {
    asm volatile("ldmatrix.sync.aligned.m8n8.x4.shared.b16 {%0,%1,%2,%3}, [%4];"
                 : "=r"(f[0]), "=r"(f[1]), "=r"(f[2]), "=r"(f[3]) : "r"(addr));
}
__device__ __forceinline__ void ldmB(uint32_t* f, uint32_t addr) {
    asm volatile("ldmatrix.sync.aligned.m8n8.x2.shared.b16 {%0,%1}, [%2];"
                 : "=r"(f[0]), "=r"(f[1]) : "r"(addr));
}
__device__ __forceinline__ void mma16816(float* c, const uint32_t* a, const uint32_t* b) {
    asm volatile("mma.sync.aligned.m16n8k16.row.col.f32.bf16.bf16.f32 "
                 "{%0,%1,%2,%3}, {%4,%5,%6,%7}, {%8,%9}, {%0,%1,%2,%3};"
                 : "+f"(c[0]), "+f"(c[1]), "+f"(c[2]), "+f"(c[3])
                 : "r"(a[0]), "r"(a[1]), "r"(a[2]), "r"(a[3]), "r"(b[0]), "r"(b[1]));
}
__device__ __forceinline__ unsigned fkey(float x) {
    unsigned u = __float_as_uint(x);
    return (u & 0x80000000u) ? ~u : (u | 0x80000000u);
}
__device__ __forceinline__ float fdec(unsigned k) {
    return (k & 0x80000000u) ? __uint_as_float(k & 0x7fffffffu) : __uint_as_float(~k);
}

// ---------------- fp32 -> bf16 convert (z and W fused) ----------------
__global__ void conv_all(const float* __restrict__ z, const float* __restrict__ W,
                         unsigned short* __restrict__ zb, unsigned short* __restrict__ wb) {
    int i = blockIdx.x * blockDim.x + threadIdx.x;
    const int nz = NB * ND / 8;
    const int nw = NK * ND / 8;
    const float* src;
    unsigned short* dst;
    int j;
    if (i < nz) { src = z; dst = zb; j = i; }
    else if (i < nz + nw) { src = W; dst = wb; j = i - nz; }
    else return;
    const float4* s = reinterpret_cast<const float4*>(src) + j * 2;
    float4 a = __ldg(s), b = __ldg(s + 1);
    uint4 o;
    o.x = (uint32_t)__bfloat16_as_ushort(__float2bfloat16_rn(a.x)) |
          ((uint32_t)__bfloat16_as_ushort(__float2bfloat16_rn(a.y)) << 16);
    o.y = (uint32_t)__bfloat16_as_ushort(__float2bfloat16_rn(a.z)) |
          ((uint32_t)__bfloat16_as_ushort(__float2bfloat16_rn(a.w)) << 16);
    o.z = (uint32_t)__bfloat16_as_ushort(__float2bfloat16_rn(b.x)) |
          ((uint32_t)__bfloat16_as_ushort(__float2bfloat16_rn(b.y)) << 16);
    o.w = (uint32_t)__bfloat16_as_ushort(__float2bfloat16_rn(b.z)) |
          ((uint32_t)__bfloat16_as_ushort(__float2bfloat16_rn(b.w)) << 16);
    reinterpret_cast<uint4*>(dst)[j] = o;
}

// ---------------- row norms (exact, sequential), z+W fused, + resets ----------------
__global__ void norm_all(const float* __restrict__ z, const float* __restrict__ W) {
    int r = blockIdx.x * blockDim.x + threadIdx.x;
    const float* src;
    int row;
    if (r < NB) { src = z; row = r; }
    else if (r < NB + NK) { src = W; row = r - NB; }
    else return;
    const float4* p = reinterpret_cast<const float4*>(src + (size_t)row * ND);
    float acc = 0.f;
#pragma unroll 4
    for (int i = 0; i < ND / 4; i++) {
        float4 v = __ldg(p + i);
        acc = __fadd_rn(acc, __fmul_rn(v.x, v.x));
        acc = __fadd_rn(acc, __fmul_rn(v.y, v.y));
        acc = __fadd_rn(acc, __fmul_rn(v.z, v.z));
        acc = __fadd_rn(acc, __fmul_rn(v.w, v.w));
    }
    if (r < NB) {
        g_znorm[r] = acc;
        g_cnt[r] = 0;
        g_rmax[r] = 0u;
        if (r == 0) g_qhead = 0;
    } else {
        g_wnorm[row] = acc;
    }
}

// ---------------- HMMA filter: r11 body + score store ----------------
#define PITCH 80          // bytes per 32-col bf16 row (64B data + 16B pad)
#define TILE_BYTES (128 * PITCH)     // 10240
#define SMEM_DYN (6 * TILE_BYTES)    // 3 x (A + B) = 61440

__global__ __launch_bounds__(256, 2) void mma_filter() {
    extern __shared__ char dsm[];
    __shared__ int s_item;

    char* sA = dsm;                    // 3 x TILE_BYTES
    char* sB = dsm + 3 * TILE_BYTES;   // 3 x TILE_BYTES

    int tid = threadIdx.x, lid = tid & 31, wid = tid >> 5;
    int wm = wid >> 2, wn = wid & 3;     // warp grid 2 (m) x 4 (n)

    uint32_t aBase = smem_u32(sA);
    uint32_t bBase = smem_u32(sB);

    int r0 = tid >> 2, c0 = tid & 3;
    int r1 = (tid + 256) >> 2, c1 = (tid + 256) & 3;

    int lt = lid >> 3, l8 = lid & 7;
    int a_row_off = l8 + (lt & 1) * 8;
    int a_col_off = (lt >> 1) * 8;
    int b_row_off = l8;
    int b_col_off = (lt & 1) * 8;

    int g = lid >> 2, tc = (lid & 3) * 2;
    int lanebase = lid & ~3;

    for (;;) {
        if (tid == 0) s_item = atomicAdd(&g_qhead, 1);
        __syncthreads();
        int item = s_item;
        if (item >= NITEMS) break;
        int m0 = (item >> 3) * 128;
        int nt0 = (item & 7) * 8;         // 8 BN-tiles of 128 cols

        for (int nti = 0; nti < 8; nti++) {
            int n0 = (nt0 + nti) * 128;
            float acc[4][4][4];
#pragma unroll
            for (int mt = 0; mt < 4; mt++)
#pragma unroll
                for (int nt = 0; nt < 4; nt++)
#pragma unroll
                    for (int q = 0; q < 4; q++) acc[mt][nt][q] = 0.f;

            // prologue: k-blocks 0 and 1 into bufs 0 and 1
#pragma unroll
            for (int p = 0; p < 2; p++) {
                int kk = p * 32;
                uint32_t aN = aBase + p * TILE_BYTES;
                uint32_t bN = bBase + p * TILE_BYTES;
                cp16(aN + r0 * PITCH + c0 * 16, g_zb + (size_t)(m0 + r0) * ND + kk + c0 * 8);
                cp16(aN + r1 * PITCH + c1 * 16, g_zb + (size_t)(m0 + r1) * ND + kk + c1 * 8);
                cp16(bN + r0 * PITCH + c0 * 16, g_wb + (size_t)(n0 + r0) * ND + kk + c0 * 8);
                cp16(bN + r1 * PITCH + c1 * 16, g_wb + (size_t)(n0 + r1) * ND + kk + c1 * 8);
                cp_commit();
            }

            for (int kb = 0; kb < 16; kb++) {
                if (kb < 15) cp_wait<1>(); else cp_wait<0>();
                __syncthreads();    // kb data visible; step kb-1 readers all done

                int cb3 = kb % 3;
                uint32_t aCur = aBase + cb3 * TILE_BYTES;
                uint32_t bCur = bBase + cb3 * TILE_BYTES;

                // ---- ks = 0 ----
                {
                    uint32_t af[4][4], bf[4][2];
#pragma unroll
                    for (int mt = 0; mt < 4; mt++) {
                        int row = wm * 64 + mt * 16 + a_row_off;
                        ldmA(af[mt], aCur + row * PITCH + a_col_off * 2);
                    }
#pragma unroll
                    for (int nt = 0; nt < 4; nt++) {
                        int row = wn * 32 + nt * 8 + b_row_off;
                        ldmB(bf[nt], bCur + row * PITCH + b_col_off * 2);
                    }
#pragma unroll
                    for (int mt = 0; mt < 4; mt++)
#pragma unroll
                        for (int nt = 0; nt < 4; nt++)
                            mma16816(acc[mt][nt], af[mt], bf[nt]);
                }

                // cp.async for kb+2 issued INSIDE the tensor phase
                if (kb + 2 < 16) {
                    int kk = (kb + 2) * 32;
                    int bi3 = (kb + 2) % 3;
                    uint32_t aN = aBase + bi3 * TILE_BYTES;
                    uint32_t bN = bBase + bi3 * TILE_BYTES;
                    cp16(aN + r0 * PITCH + c0 * 16, g_zb + (size_t)(m0 + r0) * ND + kk + c0 * 8);
                    cp16(aN + r1 * PITCH + c1 * 16, g_zb + (size_t)(m0 + r1) * ND + kk + c1 * 8);
                    cp16(bN + r0 * PITCH + c0 * 16, g_wb + (size_t)(n0 + r0) * ND + kk + c0 * 8);
                    cp16(bN + r1 * PITCH + c1 * 16, g_wb + (size_t)(n0 + r1) * ND + kk + c1 * 8);
                    cp_commit();
                }

                // ---- ks = 1 ----
                {
                    uint32_t af[4][4], bf[4][2];
#pragma unroll
                    for (int mt = 0; mt < 4; mt++) {
                        int row = wm * 64 + mt * 16 + a_row_off;
                        ldmA(af[mt], aCur + row * PITCH + (16 + a_col_off) * 2);
                    }
#pragma unroll
                    for (int nt = 0; nt < 4; nt++) {
                        int row = wn * 32 + nt * 8 + b_row_off;
                        ldmB(bf[nt], bCur + row * PITCH + (16 + b_col_off) * 2);
                    }
#pragma unroll
                    for (int mt = 0; mt < 4; mt++)
#pragma unroll
                        for (int nt = 0; nt < 4; nt++)
                            mma16816(acc[mt][nt], af[mt], bf[nt]);
                }
            }
            __syncthreads();   // readers done before next ntile/item reuses bufs

            // epilogue: 4-lane shuffle max -> one global atomicMax per row;
            // candidates stored WITH their bf16 score for final pruning.
#pragma unroll
            for (int mt = 0; mt < 4; mt++) {
#pragma unroll
                for (int h = 0; h < 2; h++) {
                    float v8[8];
                    float m8 = -1e30f;
#pragma unroll
                    for (int nt = 0; nt < 4; nt++)
#pragma unroll
                        for (int cc = 0; cc < 2; cc++) {
                            float v = acc[mt][nt][h * 2 + cc];
                            v8[nt * 2 + cc] = v;
                            m8 = fmaxf(m8, v);
                        }
                    m8 = fmaxf(m8, __shfl_xor_sync(0xffffffffu, m8, 1));
                    m8 = fmaxf(m8, __shfl_xor_sync(0xffffffffu, m8, 2));
                    int grow = m0 + wm * 64 + mt * 16 + h * 8 + g;
                    unsigned old = 0u;
                    if ((lid & 3) == 0) old = atomicMax(&g_rmax[grow], fkey(m8));
                    float cur = fmaxf(m8, fdec(old));   // fdec(0)=NaN -> picks m8
                    float th = __shfl_sync(0xffffffffu, cur, lanebase) - MARGIN_S;
#pragma unroll
                    for (int nt = 0; nt < 4; nt++)
#pragma unroll
                        for (int cc = 0; cc < 2; cc++) {
                            float v = v8[nt * 2 + cc];
                            if (v >= th) {
                                int slot = atomicAdd(&g_cnt[grow], 1);
                                if (slot < CAP) {
                                    g_cand[grow * CAP + slot] = n0 + wn * 32 + nt * 8 + tc + cc;
                                    g_cscore[grow * CAP + slot] = v;
                                }
                            }
                        }
                }
            }
        }
    }
}

// ---------------- fused exact rescoring + gather + partials ----------------
// NEW: candidates are pruned against the FINAL global row max (known now,
// since all filter CTAs completed) before the expensive exact dot. Expected
// survivors ~1-2/row vs ~13 admitted => ~8x less uncoalesced W traffic.
__global__ __launch_bounds__(256) void exact_gather(const float* __restrict__ z,
                                                    const float* __restrict__ W,
                                                    float* __restrict__ out, int out_size) {
    __shared__ float zs[8][ND];
    int wrp = threadIdx.x >> 5, lid = threadIdx.x & 31;
    int row = blockIdx.x * 8 + wrp;
    if (row >= NB) return;

    float4* zd = reinterpret_cast<float4*>(zs[wrp]);
    const float4* zsrc = reinterpret_cast<const float4*>(z + (size_t)row * ND);
#pragma unroll
    for (int i = 0; i < ND / 4 / 32; i++) zd[lid + i * 32] = __ldg(zsrc + lid + i * 32);
    __syncwarp();

    int cnt = g_cnt[row];
    float zn = g_znorm[row];
    float best = __int_as_float(0x7f800000);
    int bi = 0x7fffffff;

    if (cnt <= CAP) {
        float thfin = fdec(g_rmax[row]) - MARGIN_S;   // final global threshold
        for (int s = lid; s < cnt; s += 32) {
            if (g_cscore[row * CAP + s] < thfin) continue;   // prune
            int k = g_cand[row * CAP + s];
            const float4* wr = reinterpret_cast<const float4*>(W + (size_t)k * ND);
            float acc = 0.f;
#pragma unroll 4
            for (int d = 0; d < ND / 4; d++) {
                float4 wv = __ldg(wr + d);
                float4 zv = zd[d];
                acc = __fmaf_rn(zv.x, wv.x, acc);
                acc = __fmaf_rn(zv.y, wv.y, acc);
                acc = __fmaf_rn(zv.z, wv.z, acc);
                acc = __fmaf_rn(zv.w, wv.w, acc);
            }
            float d2 = __fsub_rn(__fadd_rn(zn, g_wnorm[k]), __fmul_rn(2.0f, acc));
            if (d2 < best || (d2 == best && k < bi)) { best = d2; bi = k; }
        }
    } else {
        for (int k = lid; k < NK; k += 32) {
            const float4* wr = reinterpret_cast<const float4*>(W + (size_t)k * ND);
            float acc = 0.f;
#pragma unroll 4
            for (int d = 0; d < ND / 4; d++) {
                float4 wv = __ldg(wr + d);
                float4 zv = zd[d];
                acc = __fmaf_rn(zv.x, wv.x, acc);
                acc = __fmaf_rn(zv.y, wv.y, acc);
                acc = __fmaf_rn(zv.z, wv.z, acc);
                acc = __fmaf_rn(zv.w, wv.w, acc);
            }
            float d2 = __fsub_rn(__fadd_rn(zn, g_wnorm[k]), __fmul_rn(2.0f, acc));
            if (d2 < best || (d2 == best && k < bi)) { best = d2; bi = k; }
        }
    }
#pragma unroll
    for (int off = 16; off > 0; off >>= 1) {
        float ov = __shfl_down_sync(0xffffffffu, best, off);
        int oi = __shfl_down_sync(0xffffffffu, bi, off);
        if (ov < best || (ov == best && oi < bi)) { best = ov; bi = oi; }
    }
    bi = __shfl_sync(0xffffffffu, bi, 0);

    // gather + straight-through rounding + loss partial (z from smem)
    const float4* wr = reinterpret_cast<const float4*>(W + (size_t)bi * ND);
    float4* od = reinterpret_cast<float4*>(out + (size_t)row * ND);
    float s = 0.f;
#pragma unroll
    for (int i = 0; i < ND / 4 / 32; i++) {
        int j = lid + i * 32;
        float4 wv = __ldg(wr + j);
        float4 zv = zd[j];
        float dx = __fsub_rn(wv.x, zv.x);
        float dy = __fsub_rn(wv.y, zv.y);
        float dz = __fsub_rn(wv.z, zv.z);
        float dw = __fsub_rn(wv.w, zv.w);
        float4 o;
        o.x = __fadd_rn(zv.x, dx);
        o.y = __fadd_rn(zv.y, dy);
        o.z = __fadd_rn(zv.z, dz);
        o.w = __fadd_rn(zv.w, dw);
        od[j] = o;
        s = __fmaf_rn(dx, dx, s);
        s = __fmaf_rn(dy, dy, s);
        s = __fmaf_rn(dz, dz, s);
        s = __fmaf_rn(dw, dw, s);
    }
#pragma unroll
    for (int off = 16; off > 0; off >>= 1)
        s += __shfl_down_sync(0xffffffffu, s, off);
    if (lid == 0) {
        g_partials[row] = s;
        size_t off = (size_t)NB * ND + row;
        if (off < (size_t)out_size) out[off] = (float)bi;
    }
}

// ---------------- final loss reduce (1024 threads, vectorized) ----------------
__global__ void loss_reduce(float* __restrict__ out, int out_size) {
    __shared__ float sm[1024];
    int t = threadIdx.x;
    const float4* p = reinterpret_cast<const float4*>(g_partials);
    float s = 0.f;
#pragma unroll
    for (int i = 0; i < NB / 4 / 1024; i++) {
        float4 v = p[t + i * 1024];
        s += v.x + v.y + v.z + v.w;
    }
    sm[t] = s;
    __syncthreads();
    for (int o = 512; o > 0; o >>= 1) {
        if (t < o) sm[t] += sm[t + o];
        __syncthreads();
    }
    if (t == 0) {
        size_t off = (size_t)NB * ND + NB;
        if (off < (size_t)out_size)
            out[off] = 1.25f * (sm[0] / (float)((size_t)NB * ND));
    }
}

// ---------------- launch ----------------
// exact_gather stays in the 4th launch slot (ncu capture) to verify the prune.
extern "C" void kernel_launch(void* const* d_in, const int* in_sizes, int n_in,
                              void* d_out, int out_size) {
    const float* z = (const float*)d_in[0];
    const float* W = (const float*)d_in[1];
    float* out = (float*)d_out;

    static int smem_set = 0;
    if (!smem_set) {
        cudaFuncSetAttribute(mma_filter, cudaFuncAttributeMaxDynamicSharedMemorySize, SMEM_DYN);
        smem_set = 1;
    }

    unsigned short* zb_ptr = nullptr;
    unsigned short* wb_ptr = nullptr;
    cudaGetSymbolAddress((void**)&zb_ptr, g_zb);
    cudaGetSymbolAddress((void**)&wb_ptr, g_wb);

    conv_all<<<((NB + NK) * (ND / 8) + 255) / 256, 256>>>(z, W, zb_ptr, wb_ptr);
    norm_all<<<(NB + NK) / 128, 128>>>(z, W);
    mma_filter<<<FILTER_GRID, 256, SMEM_DYN>>>();
    exact_gather<<<NB / 8, 256>>>(z, W, out, out_size);
    loss_reduce<<<1, 1024>>>(out, out_size);
}